// round 2
// baseline (speedup 1.0000x reference)
#include <cuda_runtime.h>
#include <cuda_bf16.h>
#include <mma.h>

using namespace nvcuda;

#define D_MODEL 512
#define RATIO   4
#define NGROUP  65536   // 262144 / 4

// Scratch for pooled [NGROUP, D_MODEL] (device-global: allocation-guard safe)
__device__ float g_pooled[(size_t)NGROUP * D_MODEL];

// ---------------------------------------------------------------------------
// Kernel 1: attention pooling. One warp per group of RATIO=4 rows.
// Each lane holds 4 float4 (16 cols) per row => whole 4x512 group in registers.
// ---------------------------------------------------------------------------
__global__ __launch_bounds__(256) void pool_kernel(
    const float* __restrict__ chunk,
    const float* __restrict__ query)
{
    int gw   = (blockIdx.x * blockDim.x + threadIdx.x) >> 5;
    int lane = threadIdx.x & 31;
    if (gw >= NGROUP) return;

    const float4* q4 = (const float4*)query;
    float4 q[4];
#pragma unroll
    for (int i = 0; i < 4; i++) q[i] = q4[lane + 32 * i];

    const float4* base = (const float4*)(chunk + (size_t)gw * RATIO * D_MODEL);

    float4 x[RATIO][4];
    float  s[RATIO];
#pragma unroll
    for (int r = 0; r < RATIO; r++) {
        float acc = 0.f;
#pragma unroll
        for (int i = 0; i < 4; i++) {
            float4 v = base[r * (D_MODEL / 4) + lane + 32 * i];
            x[r][i] = v;
            acc += v.x * q[i].x + v.y * q[i].y + v.z * q[i].z + v.w * q[i].w;
        }
#pragma unroll
        for (int off = 16; off; off >>= 1)
            acc += __shfl_xor_sync(0xffffffffu, acc, off);
        s[r] = acc * 0.04419417382415922f;  // 1/sqrt(512)
    }

    // softmax over 4 scores (identical in all lanes)
    float m = fmaxf(fmaxf(s[0], s[1]), fmaxf(s[2], s[3]));
    float wgt[RATIO], denom = 0.f;
#pragma unroll
    for (int r = 0; r < RATIO; r++) { wgt[r] = expf(s[r] - m); denom += wgt[r]; }
    float inv = 1.f / denom;
#pragma unroll
    for (int r = 0; r < RATIO; r++) wgt[r] *= inv;

    float4* outp = (float4*)(g_pooled + (size_t)gw * D_MODEL);
#pragma unroll
    for (int i = 0; i < 4; i++) {
        float4 acc;
        acc.x = wgt[0] * x[0][i].x + wgt[1] * x[1][i].x + wgt[2] * x[2][i].x + wgt[3] * x[3][i].x;
        acc.y = wgt[0] * x[0][i].y + wgt[1] * x[1][i].y + wgt[2] * x[2][i].y + wgt[3] * x[3][i].y;
        acc.z = wgt[0] * x[0][i].z + wgt[1] * x[1][i].z + wgt[2] * x[2][i].z + wgt[3] * x[3][i].z;
        acc.w = wgt[0] * x[0][i].w + wgt[1] * x[1][i].w + wgt[2] * x[2][i].w + wgt[3] * x[3][i].w;
        outp[lane + 32 * i] = acc;
    }
}

// ---------------------------------------------------------------------------
// Kernel 2: out[m][n] = sum_k pooled[m][k] * w[n][k] + b[n]   (TF32 wmma)
// Block: 128 threads (4 warps, 2x2), tile BM=64 x BN=64, BK=16.
// w rows are K-contiguous -> B tile stored [n][k] = col-major (k,n) frag.
// ---------------------------------------------------------------------------
#define BM 64
#define BN 64
#define BK 16
#define LDS_AB 20   // BK + 4 pad (80B, 16B-multiple for wmma ld)
#define LDS_C  68   // BN + 4 pad (272B, 16B-multiple)

__global__ __launch_bounds__(128) void gemm_bias_kernel(
    const float* __restrict__ W,
    const float* __restrict__ bias,
    float* __restrict__ out)
{
    __shared__ float As[BM * LDS_AB];
    __shared__ float Bs[BN * LDS_AB];
    __shared__ float Cs[BM * LDS_C];

    const float* A = g_pooled;
    int tid  = threadIdx.x;
    int warp = tid >> 5;
    int wy   = warp >> 1;      // 0..1 (m dir)
    int wx   = warp & 1;       // 0..1 (n dir)
    size_t m0 = (size_t)blockIdx.x * BM;
    int    n0 = blockIdx.y * BN;

    wmma::fragment<wmma::accumulator, 16, 16, 8, float> acc[2][2];
#pragma unroll
    for (int i = 0; i < 2; i++)
#pragma unroll
        for (int j = 0; j < 2; j++)
            wmma::fill_fragment(acc[i][j], 0.f);

    for (int k0 = 0; k0 < D_MODEL; k0 += BK) {
        __syncthreads();   // previous iteration's frag loads done before overwrite
        // Stage A (pooled) and B (w) tiles; convert to tf32 once at store time.
#pragma unroll
        for (int it = 0; it < 2; it++) {
            int f   = tid + it * 128;        // 0..255 -> 256 float4 per tile
            int row = f >> 2;                // 0..63
            int c4  = f & 3;                 // 0..3
            float4 va = *(const float4*)(A + (m0 + row) * D_MODEL + k0 + c4 * 4);
            float* da = &As[row * LDS_AB + c4 * 4];
            da[0] = wmma::__float_to_tf32(va.x);
            da[1] = wmma::__float_to_tf32(va.y);
            da[2] = wmma::__float_to_tf32(va.z);
            da[3] = wmma::__float_to_tf32(va.w);
            float4 vb = *(const float4*)(W + (size_t)(n0 + row) * D_MODEL + k0 + c4 * 4);
            float* db = &Bs[row * LDS_AB + c4 * 4];
            db[0] = wmma::__float_to_tf32(vb.x);
            db[1] = wmma::__float_to_tf32(vb.y);
            db[2] = wmma::__float_to_tf32(vb.z);
            db[3] = wmma::__float_to_tf32(vb.w);
        }
        __syncthreads();

#pragma unroll
        for (int ks = 0; ks < 2; ks++) {
            wmma::fragment<wmma::matrix_a, 16, 16, 8, wmma::precision::tf32, wmma::row_major> a_frag[2];
            wmma::fragment<wmma::matrix_b, 16, 16, 8, wmma::precision::tf32, wmma::col_major> b_frag[2];
#pragma unroll
            for (int i = 0; i < 2; i++)
                wmma::load_matrix_sync(a_frag[i], &As[(wy * 32 + i * 16) * LDS_AB + ks * 8], LDS_AB);
#pragma unroll
            for (int j = 0; j < 2; j++)
                wmma::load_matrix_sync(b_frag[j], &Bs[(wx * 32 + j * 16) * LDS_AB + ks * 8], LDS_AB);
#pragma unroll
            for (int i = 0; i < 2; i++)
#pragma unroll
                for (int j = 0; j < 2; j++)
                    wmma::mma_sync(acc[i][j], a_frag[i], b_frag[j], acc[i][j]);
        }
    }

    __syncthreads();
#pragma unroll
    for (int i = 0; i < 2; i++)
#pragma unroll
        for (int j = 0; j < 2; j++)
            wmma::store_matrix_sync(&Cs[(wy * 32 + i * 16) * LDS_C + wx * 32 + j * 16],
                                    acc[i][j], LDS_C, wmma::mem_row_major);
    __syncthreads();

    // bias add + coalesced store
    for (int e = tid; e < BM * BN; e += 128) {
        int r = e >> 6;
        int c = e & 63;
        out[(m0 + r) * D_MODEL + n0 + c] = Cs[r * LDS_C + c] + bias[n0 + c];
    }
}

// ---------------------------------------------------------------------------
extern "C" void kernel_launch(void* const* d_in, const int* in_sizes, int n_in,
                              void* d_out, int out_size)
{
    const float* chunk = (const float*)d_in[0];
    const float* query = (const float*)d_in[1];
    const float* w     = (const float*)d_in[2];
    const float* b     = (const float*)d_in[3];
    float*       out   = (float*)d_out;

    // 65536 warps, 8 warps per 256-thread block
    pool_kernel<<<NGROUP / 8, 256>>>(chunk, query);

    dim3 grid(NGROUP / BM, D_MODEL / BN);   // (1024, 8)
    gemm_bias_kernel<<<grid, 128>>>(w, b, out);
}

// round 5
// speedup vs baseline: 2.8088x; 2.8088x over previous
#include <cuda_runtime.h>
#include <cuda_fp16.h>
#include <cstdint>

#define D_MODEL 512
#define RATIO   4
#define NGROUP  65536   // 262144 / 4

// Device scratch (allocation-guard safe)
__device__ __half g_ph[(size_t)NGROUP * D_MODEL];   // pooled, fp16
__device__ __half g_wh[D_MODEL * D_MODEL];          // W, fp16

// ---------------------------------------------------------------------------
// Kernel 0: convert W to fp16
// ---------------------------------------------------------------------------
__global__ __launch_bounds__(256) void wprep_kernel(const float* __restrict__ W)
{
    int i = blockIdx.x * blockDim.x + threadIdx.x;   // 65536 float4
    float4 v = ((const float4*)W)[i];
    __half2 h01 = __floats2half2_rn(v.x, v.y);
    __half2 h23 = __floats2half2_rn(v.z, v.w);
    uint2 u;
    u.x = *reinterpret_cast<uint32_t*>(&h01);
    u.y = *reinterpret_cast<uint32_t*>(&h23);
    ((uint2*)g_wh)[i] = u;
}

// ---------------------------------------------------------------------------
// Kernel 1: attention pooling -> fp16. One warp per group of 4 rows.
// ---------------------------------------------------------------------------
__global__ __launch_bounds__(256) void pool_kernel(
    const float* __restrict__ chunk,
    const float* __restrict__ query)
{
    int gw   = (blockIdx.x * blockDim.x + threadIdx.x) >> 5;
    int lane = threadIdx.x & 31;

    const float4* q4 = (const float4*)query;
    float4 q[4];
#pragma unroll
    for (int i = 0; i < 4; i++) q[i] = q4[lane + 32 * i];

    const float4* base = (const float4*)(chunk + (size_t)gw * RATIO * D_MODEL);

    float4 x[RATIO][4];
    float  s[RATIO];
#pragma unroll
    for (int r = 0; r < RATIO; r++) {
        float acc = 0.f;
#pragma unroll
        for (int i = 0; i < 4; i++) {
            float4 v = base[r * (D_MODEL / 4) + lane + 32 * i];
            x[r][i] = v;
            acc += v.x * q[i].x + v.y * q[i].y + v.z * q[i].z + v.w * q[i].w;
        }
#pragma unroll
        for (int off = 16; off; off >>= 1)
            acc += __shfl_xor_sync(0xffffffffu, acc, off);
        s[r] = acc * 0.04419417382415922f;  // 1/sqrt(512)
    }

    float m = fmaxf(fmaxf(s[0], s[1]), fmaxf(s[2], s[3]));
    float wgt[RATIO], denom = 0.f;
#pragma unroll
    for (int r = 0; r < RATIO; r++) { wgt[r] = expf(s[r] - m); denom += wgt[r]; }
    float inv = 1.f / denom;
#pragma unroll
    for (int r = 0; r < RATIO; r++) wgt[r] *= inv;

    uint2* outp = (uint2*)(g_ph + (size_t)gw * D_MODEL);
#pragma unroll
    for (int i = 0; i < 4; i++) {
        float4 acc;
        acc.x = wgt[0]*x[0][i].x + wgt[1]*x[1][i].x + wgt[2]*x[2][i].x + wgt[3]*x[3][i].x;
        acc.y = wgt[0]*x[0][i].y + wgt[1]*x[1][i].y + wgt[2]*x[2][i].y + wgt[3]*x[3][i].y;
        acc.z = wgt[0]*x[0][i].z + wgt[1]*x[1][i].z + wgt[2]*x[2][i].z + wgt[3]*x[3][i].z;
        acc.w = wgt[0]*x[0][i].w + wgt[1]*x[1][i].w + wgt[2]*x[2][i].w + wgt[3]*x[3][i].w;
        __half2 h01 = __floats2half2_rn(acc.x, acc.y);
        __half2 h23 = __floats2half2_rn(acc.z, acc.w);
        uint2 u;
        u.x = *reinterpret_cast<uint32_t*>(&h01);
        u.y = *reinterpret_cast<uint32_t*>(&h23);
        outp[lane + 32 * i] = u;
    }
}

// ---------------------------------------------------------------------------
// Kernel 2: fp16 mma.sync GEMM.  out[m][n] = sum_k pooled[m][k]*W[n][k] + b[n]
// BM=128, BN=128, BK=64, 256 threads (8 warps, 2m x 4n), warp tile 64x32.
// 3-stage cp.async pipeline. smem row stride = 72 halfs (144B): conflict-free
// ldmatrix (36*i mod 32 distinct for i=0..7).
// ---------------------------------------------------------------------------
#define BK          64
#define ROW_HALFS   72
#define ROW_BYTES   144
#define TILE_BYTES  18432           // 128 * 144
#define STAGE_BYTES 36864           // A tile + B tile
#define NSTAGE      3
#define SMEM_TOTAL  (NSTAGE * STAGE_BYTES)   // 110592
#define KITER       8               // 512 / 64

__device__ __forceinline__ uint32_t smem_u32(const void* p) {
    uint32_t a;
    asm("{ .reg .u64 t; cvta.to.shared.u64 t, %1; cvt.u32.u64 %0, t; }"
        : "=r"(a) : "l"(p));
    return a;
}

#define LDSM4(r0, r1, r2, r3, addr) \
    asm volatile("ldmatrix.sync.aligned.m8n8.x4.shared.b16 {%0,%1,%2,%3}, [%4];" \
                 : "=r"(r0), "=r"(r1), "=r"(r2), "=r"(r3) : "r"(addr))

#define MMA16816(c, a0, a1, a2, a3, b0, b1) \
    asm volatile("mma.sync.aligned.m16n8k16.row.col.f32.f16.f16.f32 " \
                 "{%0,%1,%2,%3}, {%4,%5,%6,%7}, {%8,%9}, {%0,%1,%2,%3};" \
                 : "+f"((c)[0]), "+f"((c)[1]), "+f"((c)[2]), "+f"((c)[3]) \
                 : "r"(a0), "r"(a1), "r"(a2), "r"(a3), "r"(b0), "r"(b1))

__device__ __forceinline__ void load_stage(uint32_t sb, int s, size_t m0, int n0)
{
    const int k0 = s * BK;
    uint32_t base = sb + (uint32_t)((s % NSTAGE) * STAGE_BYTES);
    int tid = threadIdx.x;
#pragma unroll
    for (int i = 0; i < 4; i++) {
        int idx = tid + i * 256;                 // 0..1023
        int row = idx >> 3, ch = idx & 7;
        uint32_t sa = base + row * ROW_BYTES + ch * 16;
        const __half* ga = g_ph + (m0 + row) * D_MODEL + k0 + ch * 8;
        asm volatile("cp.async.cg.shared.global [%0], [%1], 16;" :: "r"(sa), "l"(ga));
    }
#pragma unroll
    for (int i = 0; i < 4; i++) {
        int idx = tid + i * 256;
        int row = idx >> 3, ch = idx & 7;
        uint32_t sbb = base + TILE_BYTES + row * ROW_BYTES + ch * 16;
        const __half* gb = g_wh + (size_t)(n0 + row) * D_MODEL + k0 + ch * 8;
        asm volatile("cp.async.cg.shared.global [%0], [%1], 16;" :: "r"(sbb), "l"(gb));
    }
    asm volatile("cp.async.commit_group;" ::: "memory");
}

__global__ __launch_bounds__(256) void gemm_kernel(
    const float* __restrict__ bias,
    float* __restrict__ out)
{
    extern __shared__ char smem[];
    uint32_t sb = smem_u32(smem);
    const int tid  = threadIdx.x;
    const int lane = tid & 31;
    const int wid  = tid >> 5;
    const int wm   = wid & 1;       // 0..1: 64-row half
    const int wn   = wid >> 1;      // 0..3: 32-col slice
    const size_t m0 = (size_t)blockIdx.x * 128;
    const int    n0 = blockIdx.y * 128;

    float acc[4][4][4];
#pragma unroll
    for (int a = 0; a < 4; a++)
#pragma unroll
        for (int b = 0; b < 4; b++)
#pragma unroll
            for (int c = 0; c < 4; c++) acc[a][b][c] = 0.f;

    load_stage(sb, 0, m0, n0);
    load_stage(sb, 1, m0, n0);

    const int rowsel = lane & 15;
    const int ksel   = (lane >> 4) * 16;   // bytes: 8 halfs

    for (int s = 0; s < KITER; s++) {
        // Pending-group allowance: stages committed = min(s+2, KITER).
        // Need stage s complete -> allowance = min(s+2,KITER)-(s+1):
        // 1 for s < KITER-1, 0 for the last iteration (this was the R4 race).
        if (s == KITER - 1)
            asm volatile("cp.async.wait_group 0;" ::: "memory");
        else
            asm volatile("cp.async.wait_group 1;" ::: "memory");
        __syncthreads();
        uint32_t base = sb + (uint32_t)((s % NSTAGE) * STAGE_BYTES);
        uint32_t abase = base + (wm * 64 + rowsel) * ROW_BYTES + ksel;
        uint32_t bbase = base + TILE_BYTES + (wn * 32 + rowsel) * ROW_BYTES + ksel;
#pragma unroll
        for (int kk = 0; kk < 4; kk++) {
            uint32_t a[4][4], b[2][4];
#pragma unroll
            for (int mf = 0; mf < 4; mf++)
                LDSM4(a[mf][0], a[mf][1], a[mf][2], a[mf][3],
                      abase + mf * (16 * ROW_BYTES) + kk * 32);
#pragma unroll
            for (int p = 0; p < 2; p++)
                LDSM4(b[p][0], b[p][1], b[p][2], b[p][3],
                      bbase + p * (16 * ROW_BYTES) + kk * 32);
#pragma unroll
            for (int mf = 0; mf < 4; mf++)
#pragma unroll
                for (int nf = 0; nf < 4; nf++) {
                    int p = nf >> 1, q = nf & 1;
                    MMA16816(acc[mf][nf], a[mf][0], a[mf][1], a[mf][2], a[mf][3],
                             b[p][q], b[p][q + 2]);
                }
        }
        if (s + 2 < KITER) load_stage(sb, s + 2, m0, n0);
    }

    // Epilogue: direct gmem stores + bias
    float2 bv[4];
#pragma unroll
    for (int nf = 0; nf < 4; nf++) {
        int c = n0 + wn * 32 + nf * 8 + (lane & 3) * 2;
        bv[nf] = *(const float2*)(bias + c);
    }
#pragma unroll
    for (int mf = 0; mf < 4; mf++) {
        size_t r = m0 + wm * 64 + mf * 16 + (lane >> 2);
#pragma unroll
        for (int nf = 0; nf < 4; nf++) {
            int c = n0 + wn * 32 + nf * 8 + (lane & 3) * 2;
            float2 o0, o1;
            o0.x = acc[mf][nf][0] + bv[nf].x;
            o0.y = acc[mf][nf][1] + bv[nf].y;
            o1.x = acc[mf][nf][2] + bv[nf].x;
            o1.y = acc[mf][nf][3] + bv[nf].y;
            *(float2*)(out + r * D_MODEL + c)       = o0;
            *(float2*)(out + (r + 8) * D_MODEL + c) = o1;
        }
    }
}

// ---------------------------------------------------------------------------
extern "C" void kernel_launch(void* const* d_in, const int* in_sizes, int n_in,
                              void* d_out, int out_size)
{
    const float* chunk = (const float*)d_in[0];
    const float* query = (const float*)d_in[1];
    const float* w     = (const float*)d_in[2];
    const float* b     = (const float*)d_in[3];
    float*       out   = (float*)d_out;

    cudaFuncSetAttribute(gemm_kernel,
                         cudaFuncAttributeMaxDynamicSharedMemorySize, SMEM_TOTAL);

    wprep_kernel<<<256, 256>>>(w);
    pool_kernel<<<NGROUP / 8, 256>>>(chunk, query);
    dim3 grid(NGROUP / 128, D_MODEL / 128);   // (512, 4)
    gemm_kernel<<<grid, 256, SMEM_TOTAL>>>(b, out);
}